// round 5
// baseline (speedup 1.0000x reference)
#include <cuda_runtime.h>
#include <cstdint>

#define H_ 512
#define W_ 512
#define G_ 83
#define KK 12
#define NB 8
#define NV (G_ * G_)                 // 6889 vertices
#define NF (2 * (G_ - 1) * (G_ - 1)) // 13448 faces
#define HW (H_ * W_)

// 8 * 262144 * 8B = 16 MB z-buffer scratch
__device__ unsigned long long g_zbuf[NB * HW];

// Strict IEEE, non-fused edge function: (a-b)*(c-d) - (e-f)*(g-h)
__device__ __forceinline__ float edgefn(float a, float b, float c, float d,
                                        float e, float f, float g, float h) {
    float t1 = __fmul_rn(__fsub_rn(a, b), __fsub_rn(c, d));
    float t2 = __fmul_rn(__fsub_rn(e, f), __fsub_rn(g, h));
    return __fsub_rn(t1, t2);
}

__global__ void init_kernel() {
    int i = blockIdx.x * blockDim.x + threadIdx.x;
    if (i < NB * HW) g_zbuf[i] = 0xFFFFFFFFFFFFFFFFull;
}

// One warp per (batch, triangle). Lanes split the 12x12 candidate window.
__global__ void raster_kernel(const float* __restrict__ verts,
                              const int* __restrict__ faces) {
    int gw = (blockIdx.x * blockDim.x + threadIdx.x) >> 5;
    int lane = threadIdx.x & 31;
    if (gw >= NB * NF) return;
    int n = gw / NF;
    int f = gw - n * NF;

    int i0 = faces[3 * f + 0];
    int i1 = faces[3 * f + 1];
    int i2 = faces[3 * f + 2];
    const float* vb = verts + (size_t)n * NV * 3;

    float z0 = vb[3 * i0 + 2], z1 = vb[3 * i1 + 2], z2 = vb[3 * i2 + 2];
    // XLA rewrites divide-by-broadcast into multiply-by-reciprocal:
    // p = v * (1/z), with 1/z correctly rounded (rcp.rn == div.rn(1,z)).
    float r0 = __fdiv_rn(1.0f, z0), r1 = __fdiv_rn(1.0f, z1), r2 = __fdiv_rn(1.0f, z2);
    float x0 = __fmul_rn(vb[3 * i0 + 0], r0), y0 = __fmul_rn(vb[3 * i0 + 1], r0);
    float x1 = __fmul_rn(vb[3 * i1 + 0], r1), y1 = __fmul_rn(vb[3 * i1 + 1], r1);
    float x2 = __fmul_rn(vb[3 * i2 + 0], r2), y2 = __fmul_rn(vb[3 * i2 + 1], r2);

    // area = (x1-x0)*(y2-y0) - (y1-y0)*(x2-x0), strict IEEE non-fused
    float area = edgefn(x1, x0, y2, y0, y1, y0, x2, x0);
    bool front = (z0 > 0.f) && (z1 > 0.f) && (z2 > 0.f);
    if (!front || !(fabsf(area) > 1e-9f)) return;
    // w = EF * (1/area): same divide-by-broadcast rewrite
    float invA = __fdiv_rn(1.0f, area);

    float bminx = floorf(fminf(x0, fminf(x1, x2)));
    float bminy = floorf(fminf(y0, fminf(y1, y2)));
    int bcx = (int)fminf(fmaxf(bminx, 0.f), (float)(W_ - KK));
    int bcy = (int)fminf(fmaxf(bminy, 0.f), (float)(H_ - KK));

    unsigned long long* zb = g_zbuf + (size_t)n * HW;
    int mbase = f * (KK * KK);

    #pragma unroll 5
    for (int it = 0; it < 5; it++) {
        int t = lane + it * 32;
        if (t >= KK * KK) break;
        int oy = t / KK;
        int ox = t - oy * KK;
        int px = bcx + ox;
        int py = bcy + oy;
        float pxf = (float)px, pyf = (float)py;
        float w0 = __fmul_rn(edgefn(x2, x1, pyf, y1, y2, y1, pxf, x1), invA);
        float w1 = __fmul_rn(edgefn(x0, x2, pyf, y2, y0, y2, pxf, x2), invA);
        float w2 = __fsub_rn(__fsub_rn(1.0f, w0), w1);
        if (w0 >= 0.f && w1 >= 0.f && w2 >= 0.f) {
            // depth = (w0*z0 + w1*z1) + w2*z2, left-assoc, non-fused
            float depth = __fadd_rn(
                __fadd_rn(__fmul_rn(w0, z0), __fmul_rn(w1, z1)),
                __fmul_rn(w2, z2));
            unsigned long long packed =
                ((unsigned long long)__float_as_uint(depth) << 32) |
                (unsigned int)(mbase + t);
            atomicMin(zb + py * W_ + px, packed);
        }
    }
}

// One thread per (batch, pixel): decode winner, recompute barycentrics with the
// SAME arithmetic, interpolate uv, apply epilogue, write uvs + mask.
__global__ void shade_kernel(const float* __restrict__ verts,
                             const int* __restrict__ faces,
                             const float* __restrict__ vals,
                             float* __restrict__ out) {
    int gid = blockIdx.x * blockDim.x + threadIdx.x;
    if (gid >= NB * HW) return;
    int n = gid / HW;
    int pix = gid - n * HW;

    unsigned long long zv = g_zbuf[gid];
    float u = 0.f, v = 0.f;
    if (zv != 0xFFFFFFFFFFFFFFFFull) {
        int m = (int)(unsigned int)(zv & 0xFFFFFFFFu);
        int f = m / (KK * KK);
        int i0 = faces[3 * f + 0];
        int i1 = faces[3 * f + 1];
        int i2 = faces[3 * f + 2];
        const float* vb = verts + (size_t)n * NV * 3;
        float z0 = vb[3 * i0 + 2], z1 = vb[3 * i1 + 2], z2 = vb[3 * i2 + 2];
        float r0 = __fdiv_rn(1.0f, z0), r1 = __fdiv_rn(1.0f, z1), r2 = __fdiv_rn(1.0f, z2);
        float x0 = __fmul_rn(vb[3 * i0 + 0], r0), y0 = __fmul_rn(vb[3 * i0 + 1], r0);
        float x1 = __fmul_rn(vb[3 * i1 + 0], r1), y1 = __fmul_rn(vb[3 * i1 + 1], r1);
        float x2 = __fmul_rn(vb[3 * i2 + 0], r2), y2 = __fmul_rn(vb[3 * i2 + 1], r2);
        float area = edgefn(x1, x0, y2, y0, y1, y0, x2, x0);
        float invA = __fdiv_rn(1.0f, area);
        int px = pix & (W_ - 1);
        int py = pix >> 9;
        float pxf = (float)px, pyf = (float)py;
        float w0 = __fmul_rn(edgefn(x2, x1, pyf, y1, y2, y1, pxf, x1), invA);
        float w1 = __fmul_rn(edgefn(x0, x2, pyf, y2, y0, y2, pxf, x2), invA);
        float w2 = __fsub_rn(__fsub_rn(1.0f, w0), w1);
        // uv = (w0*v0 + w1*v1) + w2*v2, left-assoc, non-fused
        u = __fadd_rn(
            __fadd_rn(__fmul_rn(w0, vals[2 * i0 + 0]), __fmul_rn(w1, vals[2 * i1 + 0])),
            __fmul_rn(w2, vals[2 * i2 + 0]));
        v = __fadd_rn(
            __fadd_rn(__fmul_rn(w0, vals[2 * i0 + 1]), __fmul_rn(w1, vals[2 * i1 + 1])),
            __fmul_rn(w2, vals[2 * i2 + 1]));
    }
    float mask = (u > 0.f || v > 0.f) ? 1.f : 0.f;
    float ou, ov;
    if (mask > 0.f) {
        ou = __fsub_rn(__fmul_rn(2.f, u), 1.f);
        ov = __fsub_rn(__fmul_rn(2.f, v), 1.f);
    } else {
        ou = -10.f;
        ov = -10.f;
    }
    out[((size_t)n * 2 + 0) * HW + pix] = ou;
    out[((size_t)n * 2 + 1) * HW + pix] = ov;
    out[(size_t)NB * 2 * HW + (size_t)n * HW + pix] = mask;
}

extern "C" void kernel_launch(void* const* d_in, const int* in_sizes, int n_in,
                              void* d_out, int out_size) {
    const float* verts = (const float*)d_in[0];
    const int* faces = (const int*)d_in[1];
    const float* vals = (const float*)d_in[2];
    float* out = (float*)d_out;

    (void)in_sizes; (void)n_in; (void)out_size;

    int initBlocks = (NB * HW + 255) / 256;
    init_kernel<<<initBlocks, 256>>>();

    int nwarps = NB * NF;                 // 107584 warps
    int rasterBlocks = (nwarps * 32 + 255) / 256;
    raster_kernel<<<rasterBlocks, 256>>>(verts, faces);

    int shadeBlocks = (NB * HW + 255) / 256;
    shade_kernel<<<shadeBlocks, 256>>>(verts, faces, vals, out);
}